// round 14
// baseline (speedup 1.0000x reference)
#include <cuda_runtime.h>
#include <cuda_bf16.h>
#include <cuda_fp16.h>
#include <math.h>

#define NB 4
#define NN 4096
#define CC 64
#define LOG2E 1.4426950408889634f
#define SHIFT2 (40.0f * LOG2E)

// Scratch (device globals — no allocation allowed)
__device__ __half g_Qh[NB * NN * CC];   // fp16 Q * log2(e)
__device__ __half g_Kh[NB * NN * CC];   // fp16 K
__device__ __half g_Vh[NB * NN * CC];   // fp16 V
__device__ float g_Sp[NB * 32 * NN];    // partial row sums per n-tile
__device__ float g_Ladj[NB * NN];       // -log2(rowsum) - SHIFT2
__device__ float g_Po[2][NB * NN * CC]; // fused m-half partials

// ---------------------------------------------------------------------------
// helpers
// ---------------------------------------------------------------------------
__device__ __forceinline__ float ex2(float x) {
  float y;
  asm("ex2.approx.f32 %0, %1;" : "=f"(y) : "f"(x));
  return y;
}

__device__ __forceinline__ unsigned pack_h2(float a, float b) {
  __half2 h = __floats2half2_rn(a, b);
  return *(unsigned*)&h;
}

__device__ __forceinline__ void mma_fp16(float& c0, float& c1, float& c2, float& c3,
                                         unsigned a0, unsigned a1, unsigned a2, unsigned a3,
                                         unsigned b0, unsigned b1) {
  asm volatile(
      "mma.sync.aligned.m16n8k16.row.col.f32.f16.f16.f32 "
      "{%0,%1,%2,%3},{%4,%5,%6,%7},{%8,%9},{%0,%1,%2,%3};"
      : "+f"(c0), "+f"(c1), "+f"(c2), "+f"(c3)
      : "r"(a0), "r"(a1), "r"(a2), "r"(a3), "r"(b0), "r"(b1));
}

__device__ __forceinline__ void ldsm4(unsigned& r0, unsigned& r1, unsigned& r2,
                                      unsigned& r3, const void* p) {
  unsigned addr = (unsigned)__cvta_generic_to_shared(p);
  asm volatile(
      "ldmatrix.sync.aligned.m8n8.x4.shared.b16 {%0,%1,%2,%3}, [%4];"
      : "=r"(r0), "=r"(r1), "=r"(r2), "=r"(r3)
      : "r"(addr));
}

__device__ __forceinline__ void ldsm4t(unsigned& r0, unsigned& r1, unsigned& r2,
                                       unsigned& r3, const void* p) {
  unsigned addr = (unsigned)__cvta_generic_to_shared(p);
  asm volatile(
      "ldmatrix.sync.aligned.m8n8.x4.trans.shared.b16 {%0,%1,%2,%3}, [%4];"
      : "=r"(r0), "=r"(r1), "=r"(r2), "=r"(r3)
      : "r"(addr));
}

__device__ __forceinline__ void cp16(void* smem_dst, const void* gsrc) {
  unsigned dst = (unsigned)__cvta_generic_to_shared(smem_dst);
  asm volatile("cp.async.cg.shared.global [%0], [%1], 16;" ::"r"(dst), "l"(gsrc)
               : "memory");
}

// ---------------------------------------------------------------------------
// Kernel 1: fused Q/K/V projection, W in smem. 64 rows/block.
// Q scaled by log2(e); Q,K,V all fp16.
// ---------------------------------------------------------------------------
__global__ __launch_bounds__(256) void qkv_kernel(
    const float* __restrict__ x,
    const float* __restrict__ Wq, const float* __restrict__ bq,
    const float* __restrict__ Wk, const float* __restrict__ bk,
    const float* __restrict__ Wv, const float* __restrict__ bv) {
  extern __shared__ float qsm[];
  float* xs = qsm;            // [64][65]
  float* ws = qsm + 64 * 65;  // [3][64][65]

  const int tid = threadIdx.x;
  const int row0 = blockIdx.x * 64;

  #pragma unroll
  for (int i = tid; i < 64 * 64; i += 256) {
    int r = i >> 6, c = i & 63;
    xs[r * 65 + c] = x[(size_t)(row0 + r) * 64 + c];
  }
  #pragma unroll
  for (int i = tid; i < 3 * 64 * 64; i += 256) {
    int mat = i >> 12, rem = i & 4095;
    int c = rem >> 6, f = rem & 63;
    const float* W = (mat == 0) ? Wq : (mat == 1) ? Wk : Wv;
    ws[(mat * 64 + c) * 65 + f] = W[c * 64 + f];
  }
  __syncthreads();

  const int lane = tid & 31;
  const int w = tid >> 5;
  const int f0 = lane, f1 = lane + 32;

  float aq[2][8], ak[2][8], av[2][8];
  {
    float bq0 = bq[f0], bq1 = bq[f1];
    float bk0 = bk[f0], bk1 = bk[f1];
    float bv0 = bv[f0], bv1 = bv[f1];
    #pragma unroll
    for (int i = 0; i < 8; i++) {
      aq[0][i] = bq0; aq[1][i] = bq1;
      ak[0][i] = bk0; ak[1][i] = bk1;
      av[0][i] = bv0; av[1][i] = bv1;
    }
  }

  #pragma unroll 4
  for (int c = 0; c < 64; c++) {
    float wq0 = ws[(0 * 64 + c) * 65 + f0], wq1 = ws[(0 * 64 + c) * 65 + f1];
    float wk0 = ws[(1 * 64 + c) * 65 + f0], wk1 = ws[(1 * 64 + c) * 65 + f1];
    float wv0 = ws[(2 * 64 + c) * 65 + f0], wv1 = ws[(2 * 64 + c) * 65 + f1];
    #pragma unroll
    for (int i = 0; i < 8; i++) {
      float xv = xs[(w * 8 + i) * 65 + c];
      aq[0][i] += xv * wq0; aq[1][i] += xv * wq1;
      ak[0][i] += xv * wk0; ak[1][i] += xv * wk1;
      av[0][i] += xv * wv0; av[1][i] += xv * wv1;
    }
  }

  #pragma unroll
  for (int i = 0; i < 8; i++) {
    size_t base = (size_t)(row0 + w * 8 + i) * 64;
    g_Qh[base + f0] = __float2half_rn(aq[0][i] * LOG2E);
    g_Qh[base + f1] = __float2half_rn(aq[1][i] * LOG2E);
    g_Kh[base + f0] = __float2half_rn(ak[0][i]);
    g_Kh[base + f1] = __float2half_rn(ak[1][i]);
    g_Vh[base + f0] = __float2half_rn(av[0][i]);
    g_Vh[base + f1] = __float2half_rn(av[1][i]);
  }
}

// ---------------------------------------------------------------------------
// stats: E2 tile (128m x 128n) via fp16 MMA; per-row partial sums of
// 2^(E2 - SHIFT2) -> g_Sp. No P store.
// ---------------------------------------------------------------------------
__global__ __launch_bounds__(256, 2) void stats_kernel() {
  extern __shared__ char sm1[];
  __half* qh = (__half*)sm1;                       // [128][72]
  __half* kh = (__half*)(sm1 + 128 * 72 * 2);      // [128][72]
  float* ssum = (float*)(sm1 + 2 * 128 * 72 * 2);  // [128]

  const int b = blockIdx.z;
  const int m0 = blockIdx.y * 128;
  const int n0 = blockIdx.x * 128;
  const int tid = threadIdx.x;
  const __half* Qb = g_Qh + (size_t)b * NN * CC;
  const __half* Kb = g_Kh + (size_t)b * NN * CC;

  #pragma unroll
  for (int i = tid; i < 1024; i += 256) {
    int r = i >> 3, s = i & 7;
    cp16(&qh[r * 72 + s * 8], Qb + (size_t)(m0 + r) * 64 + s * 8);
    cp16(&kh[r * 72 + s * 8], Kb + (size_t)(n0 + r) * 64 + s * 8);
  }
  asm volatile("cp.async.commit_group;" ::: "memory");
  if (tid < 128) ssum[tid] = 0.0f;
  asm volatile("cp.async.wait_group 0;" ::: "memory");
  __syncthreads();

  const int lane = tid & 31;
  const int wid = tid >> 5;
  const int gid = lane >> 2, tig = lane & 3;
  const int mw = (wid >> 1) * 32;
  const int nw = (wid & 1) * 64;

  const int lq = lane & 7;
  const int lsel = lane >> 3;
  const int row_off = lq + ((lsel & 1) ? 8 : 0);
  const int col_off = (lsel & 2) ? 8 : 0;

  float acc[2][8][4];
  #pragma unroll
  for (int t = 0; t < 2; t++)
    #pragma unroll
    for (int j = 0; j < 8; j++)
      #pragma unroll
      for (int c = 0; c < 4; c++) acc[t][j][c] = 0.0f;

  #pragma unroll
  for (int k0 = 0; k0 < 64; k0 += 16) {
    unsigned a[2][4];
    #pragma unroll
    for (int t = 0; t < 2; t++)
      ldsm4(a[t][0], a[t][1], a[t][2], a[t][3],
            &qh[(mw + t * 16 + row_off) * 72 + k0 + col_off]);

    unsigned bf[8][2];
    #pragma unroll
    for (int j2 = 0; j2 < 4; j2++) {
      unsigned r0, r1, r2, r3;
      ldsm4(r0, r1, r2, r3, &kh[(nw + j2 * 16 + row_off) * 72 + k0 + col_off]);
      bf[2 * j2][0] = r0; bf[2 * j2 + 1][0] = r1;
      bf[2 * j2][1] = r2; bf[2 * j2 + 1][1] = r3;
    }

    #pragma unroll
    for (int t = 0; t < 2; t++)
      #pragma unroll
      for (int j = 0; j < 8; j++)
        mma_fp16(acc[t][j][0], acc[t][j][1], acc[t][j][2], acc[t][j][3],
                 a[t][0], a[t][1], a[t][2], a[t][3], bf[j][0], bf[j][1]);
  }

  #pragma unroll
  for (int t = 0; t < 2; t++) {
    float s0 = 0.0f, s1 = 0.0f;
    int r0 = mw + t * 16 + gid;
    #pragma unroll
    for (int j = 0; j < 8; j++) {
      s0 += ex2(acc[t][j][0] - SHIFT2) + ex2(acc[t][j][1] - SHIFT2);
      s1 += ex2(acc[t][j][2] - SHIFT2) + ex2(acc[t][j][3] - SHIFT2);
    }
    s0 += __shfl_xor_sync(0xffffffffu, s0, 1);
    s0 += __shfl_xor_sync(0xffffffffu, s0, 2);
    s1 += __shfl_xor_sync(0xffffffffu, s1, 1);
    s1 += __shfl_xor_sync(0xffffffffu, s1, 2);
    if (tig == 0) {
      atomicAdd(&ssum[r0], s0);
      atomicAdd(&ssum[r0 + 8], s1);
    }
  }
  __syncthreads();

  if (tid < 128)
    g_Sp[((size_t)b * 32 + blockIdx.x) * NN + m0 + tid] = ssum[tid];
}

// ---------------------------------------------------------------------------
// norm: Ladj[m] = -log2(sum of 32 partials) - SHIFT2 (fixed order)
// ---------------------------------------------------------------------------
__global__ __launch_bounds__(256) void norm_kernel() {
  int r = blockIdx.x * 256 + threadIdx.x;
  int b = r >> 12, m = r & (NN - 1);
  float s = 0.0f;
  #pragma unroll
  for (int t = 0; t < 32; t++) s += g_Sp[((size_t)b * 32 + t) * NN + m];
  g_Ladj[r] = -__log2f(s) - SHIFT2;
}

// ---------------------------------------------------------------------------
// Fused pass: partial[n,c] = sum_{m in half} 2^(E2t[n,m] + Ladj[m]) * V[m,c]
// MMA1: Et = K_tile x Q_chunk^T (fp16). C-frags map register-direct onto
// MMA2's A-frags (pack fp16). MMA2: acc += P x V_chunk. ONE sync per chunk.
// Block 64n x 64c; warps: 4n x 2c (MMA1 duplicated across the c-pair).
// grid (64 n-tiles, 2 m-halves, NB) = 512 blocks.
// ---------------------------------------------------------------------------
__global__ __launch_bounds__(256, 2) void fused_kernel() {
  extern __shared__ char sm[];
  __half* kh = (__half*)sm;                              // [64][72]
  __half* qh3 = (__half*)(sm + 9216);                    // [3][64][72]
  __half* vh3 = (__half*)(sm + 9216 + 27648);            // [3][64][72]
  float* lads = (float*)(sm + 9216 + 2 * 27648);         // [3][64]

  const int half = blockIdx.y;
  const int b = blockIdx.z;
  const int n0 = blockIdx.x * 64;
  const int mbase = half * (NN / 2);
  const int tid = threadIdx.x;
  const int lane = tid & 31, wid = tid >> 5;
  const int gid = lane >> 2, tig = lane & 3;
  const int wn = (wid & 3) * 16;   // warp n-slice
  const int wc = (wid >> 2) * 32;  // warp c-slice

  const int lq = lane & 7;
  const int lsel = lane >> 3;
  const int row_off = lq + ((lsel & 1) ? 8 : 0);  // non-trans ldsm
  const int col_off = (lsel & 2) ? 8 : 0;
  const int b_row = lq + ((lsel & 1) ? 8 : 0);    // trans ldsm (V)
  const int b_col = (lsel & 2) ? 8 : 0;

  const __half* Qb = g_Qh + (size_t)b * NN * CC;
  const __half* Kb = g_Kh + (size_t)b * NN * CC;
  const __half* Vb = g_Vh + (size_t)b * NN * CC;
  const float* Lb = g_Ladj + b * NN;

  float acc[4][4];
  #pragma unroll
  for (int j = 0; j < 4; j++)
    #pragma unroll
    for (int c = 0; c < 4; c++) acc[j][c] = 0.0f;

  #define ISSUE(bufe, mce)                                                      \
    {                                                                           \
      const int _buf = (bufe);                                                  \
      const int _mc = (mce);                                                    \
      _Pragma("unroll")                                                         \
      for (int ii = tid; ii < 512; ii += 256) {                                 \
        int rr = ii >> 3, ss = ii & 7;                                          \
        cp16(&qh3[(_buf * 64 + rr) * 72 + ss * 8],                              \
             Qb + (size_t)(_mc + rr) * 64 + ss * 8);                            \
        cp16(&vh3[(_buf * 64 + rr) * 72 + ss * 8],                              \
             Vb + (size_t)(_mc + rr) * 64 + ss * 8);                            \
      }                                                                         \
      if (tid < 16) cp16(&lads[_buf * 64 + tid * 4], Lb + _mc + tid * 4);       \
      asm volatile("cp.async.commit_group;" ::: "memory");                      \
    }

  // group 0: K tile + chunk 0 ; group 1: chunk 1
  #pragma unroll
  for (int ii = tid; ii < 512; ii += 256) {
    int rr = ii >> 3, ss = ii & 7;
    cp16(&kh[rr * 72 + ss * 8], Kb + (size_t)(n0 + rr) * 64 + ss * 8);
  }
  ISSUE(0, mbase);       // commits kh + chunk0 together
  ISSUE(1, mbase + 64);

  // preload K A-fragments (held in registers for the whole kernel)
  asm volatile("cp.async.wait_group 1;" ::: "memory");
  __syncthreads();
  unsigned aK[4][4];
  #pragma unroll
  for (int ks = 0; ks < 4; ks++)
    ldsm4(aK[ks][0], aK[ks][1], aK[ks][2], aK[ks][3],
          &kh[(wn + row_off) * 72 + ks * 16 + col_off]);

  const int NCH = (NN / 2) / 64;  // 32 chunks per half
  for (int i = 0; i < NCH; i++) {
    const int b3 = i % 3;
    if (i + 1 < NCH) {
      asm volatile("cp.async.wait_group 1;" ::: "memory");
    } else {
      asm volatile("cp.async.wait_group 0;" ::: "memory");
    }
    __syncthreads();  // chunk i visible; buffer (i+2)%3 free (used at i-1)

    if (i + 2 < NCH) ISSUE((i + 2) % 3, mbase + (i + 2) * 64);

    const __half* qh = &qh3[b3 * 64 * 72];
    const __half* vh = &vh3[b3 * 64 * 72];
    const float* la = &lads[b3 * 64];

    // ---- MMA1: Et[16n x 64m] (fp16), acc1[j] cols m = j*8 + {2tig,2tig+1}
    float acc1[8][4];
    #pragma unroll
    for (int j = 0; j < 8; j++)
      #pragma unroll
      for (int c = 0; c < 4; c++) acc1[j][c] = 0.0f;

    #pragma unroll
    for (int ks = 0; ks < 4; ks++) {
      unsigned bf[8][2];
      #pragma unroll
      for (int j2 = 0; j2 < 4; j2++) {
        unsigned r0, r1, r2, r3;
        ldsm4(r0, r1, r2, r3, &qh[(j2 * 16 + row_off) * 72 + ks * 16 + col_off]);
        bf[2 * j2][0] = r0; bf[2 * j2 + 1][0] = r1;
        bf[2 * j2][1] = r2; bf[2 * j2 + 1][1] = r3;
      }
      #pragma unroll
      for (int j = 0; j < 8; j++)
        mma_fp16(acc1[j][0], acc1[j][1], acc1[j][2], acc1[j][3],
                 aK[ks][0], aK[ks][1], aK[ks][2], aK[ks][3],
                 bf[j][0], bf[j][1]);
    }

    // ---- P = 2^(Et + Ladj[m]) packed fp16, register-direct MMA2 A-frags
    unsigned pk0[8], pk1[8];
    #pragma unroll
    for (int j = 0; j < 8; j++) {
      float2 l2 = *(const float2*)&la[j * 8 + 2 * tig];
      float p0 = ex2(acc1[j][0] + l2.x);
      float p1 = ex2(acc1[j][1] + l2.y);
      float p2 = ex2(acc1[j][2] + l2.x);
      float p3 = ex2(acc1[j][3] + l2.y);
      pk0[j] = pack_h2(p0, p1);  // rows gid,   k = 2tig, 2tig+1
      pk1[j] = pack_h2(p2, p3);  // rows gid+8, same k
    }

    // ---- MMA2: acc[n(16) x c(32)] += P(k=m) x V_chunk
    #pragma unroll
    for (int ks2 = 0; ks2 < 4; ks2++) {
      unsigned a0 = pk0[2 * ks2], a1 = pk1[2 * ks2];
      unsigned a2 = pk0[2 * ks2 + 1], a3 = pk1[2 * ks2 + 1];
      #pragma unroll
      for (int cj = 0; cj < 2; cj++) {
        unsigned b00, b01, b02, b03;
        ldsm4t(b00, b01, b02, b03,
               &vh[(ks2 * 16 + b_row) * 72 + wc + cj * 16 + b_col]);
        mma_fp16(acc[cj * 2][0], acc[cj * 2][1], acc[cj * 2][2], acc[cj * 2][3],
                 a0, a1, a2, a3, b00, b01);
        mma_fp16(acc[cj * 2 + 1][0], acc[cj * 2 + 1][1], acc[cj * 2 + 1][2],
                 acc[cj * 2 + 1][3], a0, a1, a2, a3, b02, b03);
      }
    }
  }

  float* Po = g_Po[half];
  #pragma unroll
  for (int j = 0; j < 4; j++) {
    int c = wc + j * 8 + tig * 2;
    int n = n0 + wn + gid;
    size_t i0 = ((size_t)(b * NN) + n) * 64 + c;
    *(float2*)&Po[i0] = make_float2(acc[j][0], acc[j][1]);
    size_t i1 = i0 + 8 * 64;  // n + 8
    *(float2*)&Po[i1] = make_float2(acc[j][2], acc[j][3]);
  }
}

// ---------------------------------------------------------------------------
// combine: out = gamma * (Po0 + Po1) + x   (float4 vectorized)
// ---------------------------------------------------------------------------
__global__ __launch_bounds__(256) void combine_kernel(
    const float* __restrict__ x, const float* __restrict__ gamma,
    float* __restrict__ out) {
  const int i = blockIdx.x * 256 + threadIdx.x;  // < NB*NN*CC/4
  const float g = gamma[0];
  float4 p0 = ((const float4*)g_Po[0])[i];
  float4 p1 = ((const float4*)g_Po[1])[i];
  float4 xv = ((const float4*)x)[i];
  float4 o;
  o.x = g * (p0.x + p1.x) + xv.x;
  o.y = g * (p0.y + p1.y) + xv.y;
  o.z = g * (p0.z + p1.z) + xv.z;
  o.w = g * (p0.w + p1.w) + xv.w;
  ((float4*)out)[i] = o;
}

// ---------------------------------------------------------------------------
extern "C" void kernel_launch(void* const* d_in, const int* in_sizes, int n_in,
                              void* d_out, int out_size) {
  const float* x  = (const float*)d_in[0];
  const float* Wq = (const float*)d_in[1];
  const float* bq = (const float*)d_in[2];
  const float* Wk = (const float*)d_in[3];
  const float* bk = (const float*)d_in[4];
  const float* Wv = (const float*)d_in[5];
  const float* bv = (const float*)d_in[6];
  const float* gamma = (const float*)d_in[7];
  float* out = (float*)d_out;

  const int smemq = (64 * 65 + 3 * 64 * 65) * 4;         // 66560
  const int smem1 = 2 * 128 * 72 * 2 + 128 * 4;          // 37376
  const int smemf = 9216 + 2 * 27648 + 3 * 64 * 4;       // 65280
  cudaFuncSetAttribute(qkv_kernel, cudaFuncAttributeMaxDynamicSharedMemorySize, smemq);
  cudaFuncSetAttribute(stats_kernel, cudaFuncAttributeMaxDynamicSharedMemorySize, smem1);
  cudaFuncSetAttribute(fused_kernel, cudaFuncAttributeMaxDynamicSharedMemorySize, smemf);

  qkv_kernel<<<(NB * NN) / 64, 256, smemq>>>(x, Wq, bq, Wk, bk, Wv, bv);
  stats_kernel<<<dim3(NN / 128, NN / 128, NB), 256, smem1>>>();
  norm_kernel<<<(NB * NN) / 256, 256>>>();
  fused_kernel<<<dim3(NN / 64, 2, NB), 256, smemf>>>();
  combine_kernel<<<(NB * NN * CC / 4) / 256, 256>>>(x, gamma, out);
}

// round 15
// speedup vs baseline: 1.1859x; 1.1859x over previous
#include <cuda_runtime.h>
#include <cuda_bf16.h>
#include <cuda_fp16.h>
#include <math.h>

#define NB 4
#define NN 4096
#define CC 64
#define LOG2E 1.4426950408889634f
#define SHIFT2 (40.0f * LOG2E)

// Scratch (device globals — no allocation allowed)
__device__ __half g_Qh[NB * NN * CC];                // fp16 Q * log2(e)
__device__ __half g_Kh[NB * NN * CC];                // fp16 K
__device__ float g_V[NB * NN * CC];                  // full fp32
__device__ __nv_bfloat16 g_Vsb[NB * NN * CC];        // bf16(V * R)
// P buffer for ONE batch pair (67 MB — fits in 126 MB L2), reused across pairs.
// n-tile-major per local batch: P[bl][T = n/64][m][n%64]
__device__ __nv_bfloat16 g_P[(size_t)2 * NN * NN];
__device__ float g_Sp[NB * 32 * NN];                 // partial row sums per n-tile
__device__ float g_Po[2][NB * NN * CC];              // pass2 m-half partials

// ---------------------------------------------------------------------------
// helpers
// ---------------------------------------------------------------------------
__device__ __forceinline__ float ex2(float x) {
  float y;
  asm("ex2.approx.f32 %0, %1;" : "=f"(y) : "f"(x));
  return y;
}

__device__ __forceinline__ void mma_fp16(float& c0, float& c1, float& c2, float& c3,
                                         unsigned a0, unsigned a1, unsigned a2, unsigned a3,
                                         unsigned b0, unsigned b1) {
  asm volatile(
      "mma.sync.aligned.m16n8k16.row.col.f32.f16.f16.f32 "
      "{%0,%1,%2,%3},{%4,%5,%6,%7},{%8,%9},{%0,%1,%2,%3};"
      : "+f"(c0), "+f"(c1), "+f"(c2), "+f"(c3)
      : "r"(a0), "r"(a1), "r"(a2), "r"(a3), "r"(b0), "r"(b1));
}

__device__ __forceinline__ void mma_bf16(float& c0, float& c1, float& c2, float& c3,
                                         unsigned a0, unsigned a1, unsigned a2, unsigned a3,
                                         unsigned b0, unsigned b1) {
  asm volatile(
      "mma.sync.aligned.m16n8k16.row.col.f32.bf16.bf16.f32 "
      "{%0,%1,%2,%3},{%4,%5,%6,%7},{%8,%9},{%0,%1,%2,%3};"
      : "+f"(c0), "+f"(c1), "+f"(c2), "+f"(c3)
      : "r"(a0), "r"(a1), "r"(a2), "r"(a3), "r"(b0), "r"(b1));
}

__device__ __forceinline__ void ldsm4(unsigned& r0, unsigned& r1, unsigned& r2,
                                      unsigned& r3, const void* p) {
  unsigned addr = (unsigned)__cvta_generic_to_shared(p);
  asm volatile(
      "ldmatrix.sync.aligned.m8n8.x4.shared.b16 {%0,%1,%2,%3}, [%4];"
      : "=r"(r0), "=r"(r1), "=r"(r2), "=r"(r3)
      : "r"(addr));
}

__device__ __forceinline__ void ldsm4t(unsigned& r0, unsigned& r1, unsigned& r2,
                                       unsigned& r3, const void* p) {
  unsigned addr = (unsigned)__cvta_generic_to_shared(p);
  asm volatile(
      "ldmatrix.sync.aligned.m8n8.x4.trans.shared.b16 {%0,%1,%2,%3}, [%4];"
      : "=r"(r0), "=r"(r1), "=r"(r2), "=r"(r3)
      : "r"(addr));
}

__device__ __forceinline__ void cp16(void* smem_dst, const void* gsrc) {
  unsigned dst = (unsigned)__cvta_generic_to_shared(smem_dst);
  asm volatile("cp.async.cg.shared.global [%0], [%1], 16;" ::"r"(dst), "l"(gsrc)
               : "memory");
}

// ---------------------------------------------------------------------------
// Kernel 1: fused Q/K/V projection, W in smem. 64 rows/block.
// ---------------------------------------------------------------------------
__global__ __launch_bounds__(256) void qkv_kernel(
    const float* __restrict__ x,
    const float* __restrict__ Wq, const float* __restrict__ bq,
    const float* __restrict__ Wk, const float* __restrict__ bk,
    const float* __restrict__ Wv, const float* __restrict__ bv) {
  extern __shared__ float qsm[];
  float* xs = qsm;            // [64][65]
  float* ws = qsm + 64 * 65;  // [3][64][65]

  const int tid = threadIdx.x;
  const int row0 = blockIdx.x * 64;

  #pragma unroll
  for (int i = tid; i < 64 * 64; i += 256) {
    int r = i >> 6, c = i & 63;
    xs[r * 65 + c] = x[(size_t)(row0 + r) * 64 + c];
  }
  #pragma unroll
  for (int i = tid; i < 3 * 64 * 64; i += 256) {
    int mat = i >> 12, rem = i & 4095;
    int c = rem >> 6, f = rem & 63;
    const float* W = (mat == 0) ? Wq : (mat == 1) ? Wk : Wv;
    ws[(mat * 64 + c) * 65 + f] = W[c * 64 + f];
  }
  __syncthreads();

  const int lane = tid & 31;
  const int w = tid >> 5;
  const int f0 = lane, f1 = lane + 32;

  float aq[2][8], ak[2][8], av[2][8];
  {
    float bq0 = bq[f0], bq1 = bq[f1];
    float bk0 = bk[f0], bk1 = bk[f1];
    float bv0 = bv[f0], bv1 = bv[f1];
    #pragma unroll
    for (int i = 0; i < 8; i++) {
      aq[0][i] = bq0; aq[1][i] = bq1;
      ak[0][i] = bk0; ak[1][i] = bk1;
      av[0][i] = bv0; av[1][i] = bv1;
    }
  }

  #pragma unroll 4
  for (int c = 0; c < 64; c++) {
    float wq0 = ws[(0 * 64 + c) * 65 + f0], wq1 = ws[(0 * 64 + c) * 65 + f1];
    float wk0 = ws[(1 * 64 + c) * 65 + f0], wk1 = ws[(1 * 64 + c) * 65 + f1];
    float wv0 = ws[(2 * 64 + c) * 65 + f0], wv1 = ws[(2 * 64 + c) * 65 + f1];
    #pragma unroll
    for (int i = 0; i < 8; i++) {
      float xv = xs[(w * 8 + i) * 65 + c];
      aq[0][i] += xv * wq0; aq[1][i] += xv * wq1;
      ak[0][i] += xv * wk0; ak[1][i] += xv * wk1;
      av[0][i] += xv * wv0; av[1][i] += xv * wv1;
    }
  }

  #pragma unroll
  for (int i = 0; i < 8; i++) {
    size_t base = (size_t)(row0 + w * 8 + i) * 64;
    g_Qh[base + f0] = __float2half_rn(aq[0][i] * LOG2E);
    g_Qh[base + f1] = __float2half_rn(aq[1][i] * LOG2E);
    g_Kh[base + f0] = __float2half_rn(ak[0][i]);
    g_Kh[base + f1] = __float2half_rn(ak[1][i]);
    g_V[base + f0] = av[0][i];
    g_V[base + f1] = av[1][i];
  }
}

// ---------------------------------------------------------------------------
// Pass 1 (batch pair bp): E' tile (128m x 128n) via fp16 MMA;
// P = 2^(E'-SHIFT2) -> bf16 into the shared pair buffer (L2-resident);
// row partial sums -> g_Sp.
// ---------------------------------------------------------------------------
__global__ __launch_bounds__(256, 2) void pass1_kernel(int bp) {
  extern __shared__ char sm1[];
  __half* qh = (__half*)sm1;                       // [128][72]
  __half* kh = (__half*)(sm1 + 128 * 72 * 2);      // [128][72]
  float* ssum = (float*)(sm1 + 2 * 128 * 72 * 2);  // [128]
  __nv_bfloat162* ps2 = (__nv_bfloat162*)sm1;      // overlay [128][68]

  const int bl = blockIdx.z;            // local batch in pair
  const int b = bp * 2 + bl;            // global batch
  const int m0 = blockIdx.y * 128;
  const int n0 = blockIdx.x * 128;
  const int tid = threadIdx.x;
  const __half* Qb = g_Qh + (size_t)b * NN * CC;
  const __half* Kb = g_Kh + (size_t)b * NN * CC;

  #pragma unroll
  for (int i = tid; i < 1024; i += 256) {
    int r = i >> 3, s = i & 7;
    cp16(&qh[r * 72 + s * 8], Qb + (size_t)(m0 + r) * 64 + s * 8);
    cp16(&kh[r * 72 + s * 8], Kb + (size_t)(n0 + r) * 64 + s * 8);
  }
  asm volatile("cp.async.commit_group;" ::: "memory");
  if (tid < 128) ssum[tid] = 0.0f;
  asm volatile("cp.async.wait_group 0;" ::: "memory");
  __syncthreads();

  const int lane = tid & 31;
  const int wid = tid >> 5;
  const int gid = lane >> 2, tig = lane & 3;
  const int mw = (wid >> 1) * 32;
  const int nw = (wid & 1) * 64;

  const int lq = lane & 7;
  const int lsel = lane >> 3;
  const int row_off = lq + ((lsel & 1) ? 8 : 0);
  const int col_off = (lsel & 2) ? 8 : 0;

  float acc[2][8][4];
  #pragma unroll
  for (int t = 0; t < 2; t++)
    #pragma unroll
    for (int j = 0; j < 8; j++)
      #pragma unroll
      for (int c = 0; c < 4; c++) acc[t][j][c] = 0.0f;

  #pragma unroll
  for (int k0 = 0; k0 < 64; k0 += 16) {
    unsigned a[2][4];
    #pragma unroll
    for (int t = 0; t < 2; t++)
      ldsm4(a[t][0], a[t][1], a[t][2], a[t][3],
            &qh[(mw + t * 16 + row_off) * 72 + k0 + col_off]);

    unsigned bf[8][2];
    #pragma unroll
    for (int j2 = 0; j2 < 4; j2++) {
      unsigned r0, r1, r2, r3;
      ldsm4(r0, r1, r2, r3, &kh[(nw + j2 * 16 + row_off) * 72 + k0 + col_off]);
      bf[2 * j2][0] = r0; bf[2 * j2 + 1][0] = r1;
      bf[2 * j2][1] = r2; bf[2 * j2 + 1][1] = r3;
    }

    #pragma unroll
    for (int t = 0; t < 2; t++)
      #pragma unroll
      for (int j = 0; j < 8; j++)
        mma_fp16(acc[t][j][0], acc[t][j][1], acc[t][j][2], acc[t][j][3],
                 a[t][0], a[t][1], a[t][2], a[t][3], bf[j][0], bf[j][1]);
  }

  __syncthreads();  // tile reads done; safe to overlay ps2

  #pragma unroll
  for (int t = 0; t < 2; t++) {
    float s0 = 0.0f, s1 = 0.0f;
    int r0 = mw + t * 16 + gid;
    #pragma unroll
    for (int j = 0; j < 8; j++) {
      float e0 = ex2(acc[t][j][0] - SHIFT2);
      float e1 = ex2(acc[t][j][1] - SHIFT2);
      float e2 = ex2(acc[t][j][2] - SHIFT2);
      float e3 = ex2(acc[t][j][3] - SHIFT2);
      s0 += e0 + e1;
      s1 += e2 + e3;
      int cp = (nw >> 1) + j * 4 + tig;
      ps2[r0 * 68 + cp] = __floats2bfloat162_rn(e0, e1);
      ps2[(r0 + 8) * 68 + cp] = __floats2bfloat162_rn(e2, e3);
    }
    s0 += __shfl_xor_sync(0xffffffffu, s0, 1);
    s0 += __shfl_xor_sync(0xffffffffu, s0, 2);
    s1 += __shfl_xor_sync(0xffffffffu, s1, 1);
    s1 += __shfl_xor_sync(0xffffffffu, s1, 2);
    if (tig == 0) {
      atomicAdd(&ssum[r0], s0);
      atomicAdd(&ssum[r0 + 8], s1);
    }
  }
  __syncthreads();

  if (tid < 128)
    g_Sp[((size_t)b * 32 + blockIdx.x) * NN + m0 + tid] = ssum[tid];

  // drain P tile, n-tile-major into the LOCAL pair slot (L2-resident)
  uint4* GP4 = (uint4*)(g_P + (size_t)bl * NN * NN);
  const int T = n0 >> 6;
  #pragma unroll
  for (int i = tid; i < 2048; i += 256) {
    int r = i >> 4, s = i & 15;
    GP4[((size_t)(T + (s >> 3)) * NN + (m0 + r)) * 8 + (s & 7)] =
        *(const uint4*)&ps2[r * 68 + s * 4];
  }
}

// ---------------------------------------------------------------------------
// norm (batch pair bp): fused rsum + vscale (bf16 out). One warp per row.
// grid = 2*NN/8 = 1024 blocks.
// ---------------------------------------------------------------------------
__global__ __launch_bounds__(256) void norm_kernel(int bp) {
  const int rl = blockIdx.x * 8 + (threadIdx.x >> 5);  // 0 .. 2*NN-1
  const int lane = threadIdx.x & 31;
  const int b = bp * 2 + (rl >> 12);
  const int m = rl & (NN - 1);

  float s = g_Sp[((size_t)b * 32 + lane) * NN + m];
  #pragma unroll
  for (int off = 16; off; off >>= 1) s += __shfl_xor_sync(0xffffffffu, s, off);
  const float rinv = 1.0f / s;

  size_t base = ((size_t)b * NN + m) * 64;
  float v0 = g_V[base + 2 * lane], v1 = g_V[base + 2 * lane + 1];
  *(__nv_bfloat162*)&g_Vsb[base + 2 * lane] =
      __floats2bfloat162_rn(v0 * rinv, v1 * rinv);
}

// ---------------------------------------------------------------------------
// Pass 2 (batch pair bp, split-m): partial[n,c] = sum_{m in half} P*Vsb
// grid (64 n-tiles, 2 m-halves, 2 local batches) = 256 blocks.
// P read from the L2-resident pair buffer.
// ---------------------------------------------------------------------------
__global__ __launch_bounds__(256, 2) void pass2_kernel(int bp) {
  extern __shared__ char sm[];
  __nv_bfloat16* praw = (__nv_bfloat16*)sm;                      // [3][64][72]
  __nv_bfloat16* vraw = (__nv_bfloat16*)(sm + 3 * 64 * 72 * 2);  // [3][64][72]

  const int bl = blockIdx.z;
  const int b = bp * 2 + bl;
  const int half = blockIdx.y;
  const int n0 = blockIdx.x * 64;
  const int mbase = half * (NN / 2);
  const int tid = threadIdx.x;
  const int lane = tid & 31, wid = tid >> 5;
  const int gid = lane >> 2, tig = lane & 3;
  const int wn = (wid & 3) * 16;
  const int wc = (wid >> 2) * 32;

  const int lq = lane & 7;
  const int lsel = lane >> 3;
  const int a_row = lq + ((lsel & 2) ? 8 : 0);
  const int a_col = wn + ((lsel & 1) ? 8 : 0);
  const int b_row = lq + ((lsel & 1) ? 8 : 0);
  const int b_col = (lsel & 2) ? 8 : 0;

  const __nv_bfloat16* GPT =
      g_P + (size_t)bl * NN * NN + (size_t)(n0 >> 6) * NN * 64;
  const __nv_bfloat16* Vb = g_Vsb + (size_t)b * NN * CC;

  float acc[4][4];
  #pragma unroll
  for (int j = 0; j < 4; j++)
    #pragma unroll
    for (int c = 0; c < 4; c++) acc[j][c] = 0.0f;

  #define ISSUE(bufe, mce)                                                      \
    {                                                                           \
      const int _buf = (bufe);                                                  \
      const int _mc = (mce);                                                    \
      _Pragma("unroll")                                                         \
      for (int ii = tid; ii < 512; ii += 256) {                                 \
        int rr = ii >> 3, ss = ii & 7;                                          \
        cp16(&praw[(_buf * 64 + rr) * 72 + ss * 8],                             \
             GPT + ((size_t)(_mc + rr)) * 64 + ss * 8);                         \
      }                                                                         \
      _Pragma("unroll")                                                         \
      for (int ii = tid; ii < 512; ii += 256) {                                 \
        int rr = ii >> 3, ss = ii & 7;                                          \
        cp16(&vraw[(_buf * 64 + rr) * 72 + ss * 8],                             \
             Vb + (size_t)(_mc + rr) * 64 + ss * 8);                            \
      }                                                                         \
      asm volatile("cp.async.commit_group;" ::: "memory");                      \
    }

  ISSUE(0, mbase);
  ISSUE(1, mbase + 64);
  const int NCH = (NN / 2) / 64;  // 32 chunks per half
  for (int i = 0; i < NCH; i++) {
    if (i + 1 < NCH) {
      asm volatile("cp.async.wait_group 1;" ::: "memory");
    } else {
      asm volatile("cp.async.wait_group 0;" ::: "memory");
    }
    __syncthreads();  // chunk i visible; all warps done with iter i-1

    if (i + 2 < NCH) ISSUE((i + 2) % 3, mbase + (i + 2) * 64);

    const __nv_bfloat16* pb = &praw[(i % 3) * 64 * 72];
    const __nv_bfloat16* vb = &vraw[(i % 3) * 64 * 72];

    #pragma unroll
    for (int k0 = 0; k0 < 64; k0 += 16) {
      unsigned a0, a1, a2, a3;
      ldsm4t(a0, a1, a2, a3, &pb[(k0 + a_row) * 72 + a_col]);
      unsigned b00, b01, b02, b03, b10, b11, b12, b13;
      ldsm4t(b00, b01, b02, b03, &vb[(k0 + b_row) * 72 + wc + b_col]);
      ldsm4t(b10, b11, b12, b13, &vb[(k0 + b_row) * 72 + wc + 16 + b_col]);
      mma_bf16(acc[0][0], acc[0][1], acc[0][2], acc[0][3], a0, a1, a2, a3, b00, b01);
      mma_bf16(acc[1][0], acc[1][1], acc[1][2], acc[1][3], a0, a1, a2, a3, b02, b03);
      mma_bf16(acc[2][0], acc[2][1], acc[2][2], acc[2][3], a0, a1, a2, a3, b10, b11);
      mma_bf16(acc[3][0], acc[3][1], acc[3][2], acc[3][3], a0, a1, a2, a3, b12, b13);
    }
  }

  float* Po = g_Po[half];
  #pragma unroll
  for (int j = 0; j < 4; j++) {
    int c = wc + j * 8 + tig * 2;
    int n = n0 + wn + gid;
    size_t i0 = ((size_t)b * NN + n) * 64 + c;
    *(float2*)&Po[i0] = make_float2(acc[j][0], acc[j][1]);
    size_t i1 = i0 + 8 * 64;
    *(float2*)&Po[i1] = make_float2(acc[j][2], acc[j][3]);
  }
}

// ---------------------------------------------------------------------------
// combine: out = gamma * (Po0 + Po1) + x   (float4 vectorized)
// ---------------------------------------------------------------------------
__global__ __launch_bounds__(256) void combine_kernel(
    const float* __restrict__ x, const float* __restrict__ gamma,
    float* __restrict__ out) {
  const int i = blockIdx.x * 256 + threadIdx.x;  // < NB*NN*CC/4
  const float g = gamma[0];
  float4 p0 = ((const float4*)g_Po[0])[i];
  float4 p1 = ((const float4*)g_Po[1])[i];
  float4 xv = ((const float4*)x)[i];
  float4 o;
  o.x = g * (p0.x + p1.x) + xv.x;
  o.y = g * (p0.y + p1.y) + xv.y;
  o.z = g * (p0.z + p1.z) + xv.z;
  o.w = g * (p0.w + p1.w) + xv.w;
  ((float4*)out)[i] = o;
}

// ---------------------------------------------------------------------------
extern "C" void kernel_launch(void* const* d_in, const int* in_sizes, int n_in,
                              void* d_out, int out_size) {
  const float* x  = (const float*)d_in[0];
  const float* Wq = (const float*)d_in[1];
  const float* bq = (const float*)d_in[2];
  const float* Wk = (const float*)d_in[3];
  const float* bk = (const float*)d_in[4];
  const float* Wv = (const float*)d_in[5];
  const float* bv = (const float*)d_in[6];
  const float* gamma = (const float*)d_in[7];
  float* out = (float*)d_out;

  const int smemq = (64 * 65 + 3 * 64 * 65) * 4;  // 66560
  const int smem1 = 2 * 128 * 72 * 2 + 128 * 4;   // 37376
  const int smem2 = 2 * 3 * 64 * 72 * 2;          // 55296
  cudaFuncSetAttribute(qkv_kernel, cudaFuncAttributeMaxDynamicSharedMemorySize, smemq);
  cudaFuncSetAttribute(pass1_kernel, cudaFuncAttributeMaxDynamicSharedMemorySize, smem1);
  cudaFuncSetAttribute(pass2_kernel, cudaFuncAttributeMaxDynamicSharedMemorySize, smem2);

  qkv_kernel<<<(NB * NN) / 64, 256, smemq>>>(x, Wq, bq, Wk, bk, Wv, bv);
  for (int bp = 0; bp < 2; bp++) {
    pass1_kernel<<<dim3(NN / 128, NN / 128, 2), 256, smem1>>>(bp);
    norm_kernel<<<(2 * NN) / 8, 256>>>(bp);
    pass2_kernel<<<dim3(NN / 64, 2, 2), 256, smem2>>>(bp);
  }
  combine_kernel<<<(NB * NN * CC / 4) / 256, 256>>>(x, gamma, out);
}

// round 16
// speedup vs baseline: 1.2792x; 1.0787x over previous
#include <cuda_runtime.h>
#include <cuda_bf16.h>
#include <cuda_fp16.h>
#include <math.h>

#define NB 4
#define NN 4096
#define CC 64
#define LOG2E 1.4426950408889634f
#define SHIFT2 (40.0f * LOG2E)

// Scratch (device globals — no allocation allowed)
__device__ __half g_Qh[NB * NN * CC];                // fp16 Q * log2(e)
__device__ __half g_Kh[NB * NN * CC];                // fp16 K
__device__ float g_V[NB * NN * CC];                  // full fp32
__device__ __nv_bfloat16 g_Vsb[NB * NN * CC];        // bf16(V * R)
// P stored n-tile-major: P[b][T = n/64][m][n%64] (contiguous pass2 chunks)
__device__ __nv_bfloat16 g_P[(size_t)NB * NN * NN];
__device__ float g_Sp[NB * 32 * NN];                 // partial row sums per n-tile

// ---------------------------------------------------------------------------
// helpers
// ---------------------------------------------------------------------------
__device__ __forceinline__ float ex2(float x) {
  float y;
  asm("ex2.approx.f32 %0, %1;" : "=f"(y) : "f"(x));
  return y;
}

__device__ __forceinline__ void mma_fp16(float& c0, float& c1, float& c2, float& c3,
                                         unsigned a0, unsigned a1, unsigned a2, unsigned a3,
                                         unsigned b0, unsigned b1) {
  asm volatile(
      "mma.sync.aligned.m16n8k16.row.col.f32.f16.f16.f32 "
      "{%0,%1,%2,%3},{%4,%5,%6,%7},{%8,%9},{%0,%1,%2,%3};"
      : "+f"(c0), "+f"(c1), "+f"(c2), "+f"(c3)
      : "r"(a0), "r"(a1), "r"(a2), "r"(a3), "r"(b0), "r"(b1));
}

__device__ __forceinline__ void mma_bf16(float& c0, float& c1, float& c2, float& c3,
                                         unsigned a0, unsigned a1, unsigned a2, unsigned a3,
                                         unsigned b0, unsigned b1) {
  asm volatile(
      "mma.sync.aligned.m16n8k16.row.col.f32.bf16.bf16.f32 "
      "{%0,%1,%2,%3},{%4,%5,%6,%7},{%8,%9},{%0,%1,%2,%3};"
      : "+f"(c0), "+f"(c1), "+f"(c2), "+f"(c3)
      : "r"(a0), "r"(a1), "r"(a2), "r"(a3), "r"(b0), "r"(b1));
}

__device__ __forceinline__ void ldsm4(unsigned& r0, unsigned& r1, unsigned& r2,
                                      unsigned& r3, const void* p) {
  unsigned addr = (unsigned)__cvta_generic_to_shared(p);
  asm volatile(
      "ldmatrix.sync.aligned.m8n8.x4.shared.b16 {%0,%1,%2,%3}, [%4];"
      : "=r"(r0), "=r"(r1), "=r"(r2), "=r"(r3)
      : "r"(addr));
}

__device__ __forceinline__ void ldsm4t(unsigned& r0, unsigned& r1, unsigned& r2,
                                       unsigned& r3, const void* p) {
  unsigned addr = (unsigned)__cvta_generic_to_shared(p);
  asm volatile(
      "ldmatrix.sync.aligned.m8n8.x4.trans.shared.b16 {%0,%1,%2,%3}, [%4];"
      : "=r"(r0), "=r"(r1), "=r"(r2), "=r"(r3)
      : "r"(addr));
}

__device__ __forceinline__ void cp16(void* smem_dst, const void* gsrc) {
  unsigned dst = (unsigned)__cvta_generic_to_shared(smem_dst);
  asm volatile("cp.async.cg.shared.global [%0], [%1], 16;" ::"r"(dst), "l"(gsrc)
               : "memory");
}

// ---------------------------------------------------------------------------
// Kernel 1: fused Q/K/V projection, W in smem. 64 rows/block.
// ---------------------------------------------------------------------------
__global__ __launch_bounds__(256) void qkv_kernel(
    const float* __restrict__ x,
    const float* __restrict__ Wq, const float* __restrict__ bq,
    const float* __restrict__ Wk, const float* __restrict__ bk,
    const float* __restrict__ Wv, const float* __restrict__ bv) {
  extern __shared__ float qsm[];
  float* xs = qsm;            // [64][65]
  float* ws = qsm + 64 * 65;  // [3][64][65]

  const int tid = threadIdx.x;
  const int row0 = blockIdx.x * 64;

  #pragma unroll
  for (int i = tid; i < 64 * 64; i += 256) {
    int r = i >> 6, c = i & 63;
    xs[r * 65 + c] = x[(size_t)(row0 + r) * 64 + c];
  }
  #pragma unroll
  for (int i = tid; i < 3 * 64 * 64; i += 256) {
    int mat = i >> 12, rem = i & 4095;
    int c = rem >> 6, f = rem & 63;
    const float* W = (mat == 0) ? Wq : (mat == 1) ? Wk : Wv;
    ws[(mat * 64 + c) * 65 + f] = W[c * 64 + f];
  }
  __syncthreads();

  const int lane = tid & 31;
  const int w = tid >> 5;
  const int f0 = lane, f1 = lane + 32;

  float aq[2][8], ak[2][8], av[2][8];
  {
    float bq0 = bq[f0], bq1 = bq[f1];
    float bk0 = bk[f0], bk1 = bk[f1];
    float bv0 = bv[f0], bv1 = bv[f1];
    #pragma unroll
    for (int i = 0; i < 8; i++) {
      aq[0][i] = bq0; aq[1][i] = bq1;
      ak[0][i] = bk0; ak[1][i] = bk1;
      av[0][i] = bv0; av[1][i] = bv1;
    }
  }

  #pragma unroll 4
  for (int c = 0; c < 64; c++) {
    float wq0 = ws[(0 * 64 + c) * 65 + f0], wq1 = ws[(0 * 64 + c) * 65 + f1];
    float wk0 = ws[(1 * 64 + c) * 65 + f0], wk1 = ws[(1 * 64 + c) * 65 + f1];
    float wv0 = ws[(2 * 64 + c) * 65 + f0], wv1 = ws[(2 * 64 + c) * 65 + f1];
    #pragma unroll
    for (int i = 0; i < 8; i++) {
      float xv = xs[(w * 8 + i) * 65 + c];
      aq[0][i] += xv * wq0; aq[1][i] += xv * wq1;
      ak[0][i] += xv * wk0; ak[1][i] += xv * wk1;
      av[0][i] += xv * wv0; av[1][i] += xv * wv1;
    }
  }

  #pragma unroll
  for (int i = 0; i < 8; i++) {
    size_t base = (size_t)(row0 + w * 8 + i) * 64;
    g_Qh[base + f0] = __float2half_rn(aq[0][i] * LOG2E);
    g_Qh[base + f1] = __float2half_rn(aq[1][i] * LOG2E);
    g_Kh[base + f0] = __float2half_rn(ak[0][i]);
    g_Kh[base + f1] = __float2half_rn(ak[1][i]);
    g_V[base + f0] = av[0][i];
    g_V[base + f1] = av[1][i];
  }
}

// ---------------------------------------------------------------------------
// Pass 1: E' tile (128m x 128n) via fp16 MMA; P = 2^(E'-SHIFT2) -> bf16
// n-tile-major; row partial sums -> g_Sp.
// ---------------------------------------------------------------------------
__global__ __launch_bounds__(256, 2) void pass1_kernel() {
  extern __shared__ char sm1[];
  __half* qh = (__half*)sm1;                       // [128][72]
  __half* kh = (__half*)(sm1 + 128 * 72 * 2);      // [128][72]
  float* ssum = (float*)(sm1 + 2 * 128 * 72 * 2);  // [128]
  __nv_bfloat162* ps2 = (__nv_bfloat162*)sm1;      // overlay [128][68]

  const int b = blockIdx.z;
  const int m0 = blockIdx.y * 128;
  const int n0 = blockIdx.x * 128;
  const int tid = threadIdx.x;
  const __half* Qb = g_Qh + (size_t)b * NN * CC;
  const __half* Kb = g_Kh + (size_t)b * NN * CC;

  #pragma unroll
  for (int i = tid; i < 1024; i += 256) {
    int r = i >> 3, s = i & 7;
    cp16(&qh[r * 72 + s * 8], Qb + (size_t)(m0 + r) * 64 + s * 8);
    cp16(&kh[r * 72 + s * 8], Kb + (size_t)(n0 + r) * 64 + s * 8);
  }
  asm volatile("cp.async.commit_group;" ::: "memory");
  if (tid < 128) ssum[tid] = 0.0f;
  asm volatile("cp.async.wait_group 0;" ::: "memory");
  __syncthreads();

  const int lane = tid & 31;
  const int wid = tid >> 5;
  const int gid = lane >> 2, tig = lane & 3;
  const int mw = (wid >> 1) * 32;
  const int nw = (wid & 1) * 64;

  const int lq = lane & 7;
  const int lsel = lane >> 3;
  const int row_off = lq + ((lsel & 1) ? 8 : 0);
  const int col_off = (lsel & 2) ? 8 : 0;

  float acc[2][8][4];
  #pragma unroll
  for (int t = 0; t < 2; t++)
    #pragma unroll
    for (int j = 0; j < 8; j++)
      #pragma unroll
      for (int c = 0; c < 4; c++) acc[t][j][c] = 0.0f;

  #pragma unroll
  for (int k0 = 0; k0 < 64; k0 += 16) {
    unsigned a[2][4];
    #pragma unroll
    for (int t = 0; t < 2; t++)
      ldsm4(a[t][0], a[t][1], a[t][2], a[t][3],
            &qh[(mw + t * 16 + row_off) * 72 + k0 + col_off]);

    unsigned bf[8][2];
    #pragma unroll
    for (int j2 = 0; j2 < 4; j2++) {
      unsigned r0, r1, r2, r3;
      ldsm4(r0, r1, r2, r3, &kh[(nw + j2 * 16 + row_off) * 72 + k0 + col_off]);
      bf[2 * j2][0] = r0; bf[2 * j2 + 1][0] = r1;
      bf[2 * j2][1] = r2; bf[2 * j2 + 1][1] = r3;
    }

    #pragma unroll
    for (int t = 0; t < 2; t++)
      #pragma unroll
      for (int j = 0; j < 8; j++)
        mma_fp16(acc[t][j][0], acc[t][j][1], acc[t][j][2], acc[t][j][3],
                 a[t][0], a[t][1], a[t][2], a[t][3], bf[j][0], bf[j][1]);
  }

  __syncthreads();  // tile reads done; safe to overlay ps2

  #pragma unroll
  for (int t = 0; t < 2; t++) {
    float s0 = 0.0f, s1 = 0.0f;
    int r0 = mw + t * 16 + gid;
    #pragma unroll
    for (int j = 0; j < 8; j++) {
      float e0 = ex2(acc[t][j][0] - SHIFT2);
      float e1 = ex2(acc[t][j][1] - SHIFT2);
      float e2 = ex2(acc[t][j][2] - SHIFT2);
      float e3 = ex2(acc[t][j][3] - SHIFT2);
      s0 += e0 + e1;
      s1 += e2 + e3;
      int cp = (nw >> 1) + j * 4 + tig;
      ps2[r0 * 68 + cp] = __floats2bfloat162_rn(e0, e1);
      ps2[(r0 + 8) * 68 + cp] = __floats2bfloat162_rn(e2, e3);
    }
    s0 += __shfl_xor_sync(0xffffffffu, s0, 1);
    s0 += __shfl_xor_sync(0xffffffffu, s0, 2);
    s1 += __shfl_xor_sync(0xffffffffu, s1, 1);
    s1 += __shfl_xor_sync(0xffffffffu, s1, 2);
    if (tig == 0) {
      atomicAdd(&ssum[r0], s0);
      atomicAdd(&ssum[r0 + 8], s1);
    }
  }
  __syncthreads();

  if (tid < 128)
    g_Sp[((size_t)b * 32 + blockIdx.x) * NN + m0 + tid] = ssum[tid];

  uint4* GP4 = (uint4*)(g_P + (size_t)b * NN * NN);
  const int T = n0 >> 6;
  #pragma unroll
  for (int i = tid; i < 2048; i += 256) {
    int r = i >> 4, s = i & 15;
    GP4[((size_t)(T + (s >> 3)) * NN + (m0 + r)) * 8 + (s & 7)] =
        *(const uint4*)&ps2[r * 68 + s * 4];
  }
}

// ---------------------------------------------------------------------------
// norm: fused rsum + vscale (bf16 out). One warp per row.
// ---------------------------------------------------------------------------
__global__ __launch_bounds__(256) void norm_kernel() {
  const int row = blockIdx.x * 8 + (threadIdx.x >> 5);  // < NB*NN
  const int lane = threadIdx.x & 31;
  const int b = row >> 12, m = row & (NN - 1);

  float s = g_Sp[((size_t)b * 32 + lane) * NN + m];
  #pragma unroll
  for (int off = 16; off; off >>= 1) s += __shfl_xor_sync(0xffffffffu, s, off);
  const float rinv = 1.0f / s;

  size_t base = (size_t)row * 64;
  float v0 = g_V[base + 2 * lane], v1 = g_V[base + 2 * lane + 1];
  *(__nv_bfloat162*)&g_Vsb[base + 2 * lane] =
      __floats2bfloat162_rn(v0 * rinv, v1 * rinv);
}

// ---------------------------------------------------------------------------
// Pass 2: out[n,c] = gamma * sum_m P[m,n]*Vsb[m,c] + x[n,c]
// 64n x 64c tile; m-chunks of 128 rows (32 iterations), 3 buffers
// (smem 110592 B, 2 CTAs/SM), single __syncthreads per chunk.
// ---------------------------------------------------------------------------
#define MC 128
__global__ __launch_bounds__(256, 2) void pass2_kernel(
    const float* __restrict__ x, const float* __restrict__ gamma,
    float* __restrict__ out) {
  extern __shared__ char sm[];
  __nv_bfloat16* praw = (__nv_bfloat16*)sm;                       // [3][128][72]
  __nv_bfloat16* vraw = (__nv_bfloat16*)(sm + 3 * MC * 72 * 2);   // [3][128][72]

  const int b = blockIdx.y;
  const int n0 = blockIdx.x * 64;
  const int tid = threadIdx.x;
  const int lane = tid & 31, wid = tid >> 5;
  const int gid = lane >> 2, tig = lane & 3;
  const int wn = (wid & 3) * 16;
  const int wc = (wid >> 2) * 32;

  const int lq = lane & 7;
  const int lsel = lane >> 3;
  const int a_row = lq + ((lsel & 2) ? 8 : 0);
  const int a_col = wn + ((lsel & 1) ? 8 : 0);
  const int b_row = lq + ((lsel & 1) ? 8 : 0);
  const int b_col = (lsel & 2) ? 8 : 0;

  // n-tile-major P base for this block's tile T = n0/64:
  const __nv_bfloat16* GPT =
      g_P + (size_t)b * NN * NN + (size_t)(n0 >> 6) * NN * 64;
  const __nv_bfloat16* Vb = g_Vsb + (size_t)b * NN * CC;

  float acc[4][4];
  #pragma unroll
  for (int j = 0; j < 4; j++)
    #pragma unroll
    for (int c = 0; c < 4; c++) acc[j][c] = 0.0f;

  #define ISSUE(bufe, mce)                                                      \
    {                                                                           \
      const int _buf = (bufe);                                                  \
      const int _mc = (mce);                                                    \
      _Pragma("unroll")                                                         \
      for (int ii = tid; ii < MC * 8; ii += 256) {                              \
        int rr = ii >> 3, ss = ii & 7;                                          \
        cp16(&praw[(_buf * MC + rr) * 72 + ss * 8],                             \
             GPT + ((size_t)(_mc + rr)) * 64 + ss * 8);                         \
      }                                                                         \
      _Pragma("unroll")                                                         \
      for (int ii = tid; ii < MC * 8; ii += 256) {                              \
        int rr = ii >> 3, ss = ii & 7;                                          \
        cp16(&vraw[(_buf * MC + rr) * 72 + ss * 8],                             \
             Vb + (size_t)(_mc + rr) * 64 + ss * 8);                            \
      }                                                                         \
      asm volatile("cp.async.commit_group;" ::: "memory");                      \
    }

  ISSUE(0, 0);
  ISSUE(1, MC);
  const int NCH = NN / MC;  // 32 chunks
  for (int i = 0; i < NCH; i++) {
    if (i + 1 < NCH) {
      asm volatile("cp.async.wait_group 1;" ::: "memory");
    } else {
      asm volatile("cp.async.wait_group 0;" ::: "memory");
    }
    __syncthreads();  // chunk i visible to all; all warps done with iter i-1

    if (i + 2 < NCH) ISSUE((i + 2) % 3, (i + 2) * MC);

    const __nv_bfloat16* pb = &praw[(i % 3) * MC * 72];
    const __nv_bfloat16* vb = &vraw[(i % 3) * MC * 72];

    #pragma unroll
    for (int k0 = 0; k0 < MC; k0 += 16) {
      unsigned a0, a1, a2, a3;
      ldsm4t(a0, a1, a2, a3, &pb[(k0 + a_row) * 72 + a_col]);
      unsigned b00, b01, b02, b03, b10, b11, b12, b13;
      ldsm4t(b00, b01, b02, b03, &vb[(k0 + b_row) * 72 + wc + b_col]);
      ldsm4t(b10, b11, b12, b13, &vb[(k0 + b_row) * 72 + wc + 16 + b_col]);
      mma_bf16(acc[0][0], acc[0][1], acc[0][2], acc[0][3], a0, a1, a2, a3, b00, b01);
      mma_bf16(acc[1][0], acc[1][1], acc[1][2], acc[1][3], a0, a1, a2, a3, b02, b03);
      mma_bf16(acc[2][0], acc[2][1], acc[2][2], acc[2][3], a0, a1, a2, a3, b10, b11);
      mma_bf16(acc[3][0], acc[3][1], acc[3][2], acc[3][3], a0, a1, a2, a3, b12, b13);
    }
  }

  const float g = gamma[0];
  #pragma unroll
  for (int j = 0; j < 4; j++) {
    int c = wc + j * 8 + tig * 2;
    int n = n0 + wn + gid;
    size_t i0 = ((size_t)(b * NN) + n) * 64 + c;
    float2 xv = *(const float2*)&x[i0];
    float2 o;
    o.x = g * acc[j][0] + xv.x;
    o.y = g * acc[j][1] + xv.y;
    *(float2*)&out[i0] = o;
    size_t i1 = i0 + 8 * 64;
    float2 xv1 = *(const float2*)&x[i1];
    float2 o1;
    o1.x = g * acc[j][2] + xv1.x;
    o1.y = g * acc[j][3] + xv1.y;
    *(float2*)&out[i1] = o1;
  }
}

// ---------------------------------------------------------------------------
extern "C" void kernel_launch(void* const* d_in, const int* in_sizes, int n_in,
                              void* d_out, int out_size) {
  const float* x  = (const float*)d_in[0];
  const float* Wq = (const float*)d_in[1];
  const float* bq = (const float*)d_in[2];
  const float* Wk = (const float*)d_in[3];
  const float* bk = (const float*)d_in[4];
  const float* Wv = (const float*)d_in[5];
  const float* bv = (const float*)d_in[6];
  const float* gamma = (const float*)d_in[7];
  float* out = (float*)d_out;

  const int smemq = (64 * 65 + 3 * 64 * 65) * 4;  // 66560
  const int smem1 = 2 * 128 * 72 * 2 + 128 * 4;   // 37376
  const int smem2 = 2 * 3 * MC * 72 * 2;          // 110592
  cudaFuncSetAttribute(qkv_kernel, cudaFuncAttributeMaxDynamicSharedMemorySize, smemq);
  cudaFuncSetAttribute(pass1_kernel, cudaFuncAttributeMaxDynamicSharedMemorySize, smem1);
  cudaFuncSetAttribute(pass2_kernel, cudaFuncAttributeMaxDynamicSharedMemorySize, smem2);

  qkv_kernel<<<(NB * NN) / 64, 256, smemq>>>(x, Wq, bq, Wk, bk, Wv, bv);
  pass1_kernel<<<dim3(NN / 128, NN / 128, NB), 256, smem1>>>();
  norm_kernel<<<(NB * NN) / 8, 256>>>();
  pass2_kernel<<<dim3(NN / 64, NB), 256, smem2>>>(x, gamma, out);
}

// round 17
// speedup vs baseline: 1.3914x; 1.0877x over previous
#include <cuda_runtime.h>
#include <cuda_bf16.h>
#include <cuda_fp16.h>
#include <math.h>

#define NB 4
#define NN 4096
#define CC 64
#define LOG2E 1.4426950408889634f
#define SHIFT2 (40.0f * LOG2E)

// Scratch (device globals — no allocation allowed)
__device__ __half g_Qh[NB * NN * CC];                // fp16 Q * log2(e)
__device__ __half g_Kh[NB * NN * CC];                // fp16 K
__device__ float g_V[NB * NN * CC];                  // full fp32
__device__ __nv_bfloat16 g_Vsb[NB * NN * CC];        // bf16(V * R)
// P stored n-tile-major: P[b][T = n/64][m][n%64]
__device__ __nv_bfloat16 g_P[(size_t)NB * NN * NN];
__device__ float g_Sp[NB * 32 * NN];                 // partial row sums per n-tile
__device__ float g_Po[4][NB * NN * CC];              // pass2 m-quarter partials

// ---------------------------------------------------------------------------
// helpers
// ---------------------------------------------------------------------------
__device__ __forceinline__ float ex2(float x) {
  float y;
  asm("ex2.approx.f32 %0, %1;" : "=f"(y) : "f"(x));
  return y;
}

__device__ __forceinline__ void mma_fp16(float& c0, float& c1, float& c2, float& c3,
                                         unsigned a0, unsigned a1, unsigned a2, unsigned a3,
                                         unsigned b0, unsigned b1) {
  asm volatile(
      "mma.sync.aligned.m16n8k16.row.col.f32.f16.f16.f32 "
      "{%0,%1,%2,%3},{%4,%5,%6,%7},{%8,%9},{%0,%1,%2,%3};"
      : "+f"(c0), "+f"(c1), "+f"(c2), "+f"(c3)
      : "r"(a0), "r"(a1), "r"(a2), "r"(a3), "r"(b0), "r"(b1));
}

__device__ __forceinline__ void mma_bf16(float& c0, float& c1, float& c2, float& c3,
                                         unsigned a0, unsigned a1, unsigned a2, unsigned a3,
                                         unsigned b0, unsigned b1) {
  asm volatile(
      "mma.sync.aligned.m16n8k16.row.col.f32.bf16.bf16.f32 "
      "{%0,%1,%2,%3},{%4,%5,%6,%7},{%8,%9},{%0,%1,%2,%3};"
      : "+f"(c0), "+f"(c1), "+f"(c2), "+f"(c3)
      : "r"(a0), "r"(a1), "r"(a2), "r"(a3), "r"(b0), "r"(b1));
}

__device__ __forceinline__ void ldsm4(unsigned& r0, unsigned& r1, unsigned& r2,
                                      unsigned& r3, const void* p) {
  unsigned addr = (unsigned)__cvta_generic_to_shared(p);
  asm volatile(
      "ldmatrix.sync.aligned.m8n8.x4.shared.b16 {%0,%1,%2,%3}, [%4];"
      : "=r"(r0), "=r"(r1), "=r"(r2), "=r"(r3)
      : "r"(addr));
}

__device__ __forceinline__ void ldsm4t(unsigned& r0, unsigned& r1, unsigned& r2,
                                       unsigned& r3, const void* p) {
  unsigned addr = (unsigned)__cvta_generic_to_shared(p);
  asm volatile(
      "ldmatrix.sync.aligned.m8n8.x4.trans.shared.b16 {%0,%1,%2,%3}, [%4];"
      : "=r"(r0), "=r"(r1), "=r"(r2), "=r"(r3)
      : "r"(addr));
}

__device__ __forceinline__ void cp16(void* smem_dst, const void* gsrc) {
  unsigned dst = (unsigned)__cvta_generic_to_shared(smem_dst);
  asm volatile("cp.async.cg.shared.global [%0], [%1], 16;" ::"r"(dst), "l"(gsrc)
               : "memory");
}

// ---------------------------------------------------------------------------
// Kernel 1: fused Q/K/V projection, W in smem. 64 rows/block.
// ---------------------------------------------------------------------------
__global__ __launch_bounds__(256) void qkv_kernel(
    const float* __restrict__ x,
    const float* __restrict__ Wq, const float* __restrict__ bq,
    const float* __restrict__ Wk, const float* __restrict__ bk,
    const float* __restrict__ Wv, const float* __restrict__ bv) {
  extern __shared__ float qsm[];
  float* xs = qsm;            // [64][65]
  float* ws = qsm + 64 * 65;  // [3][64][65]

  const int tid = threadIdx.x;
  const int row0 = blockIdx.x * 64;

  #pragma unroll
  for (int i = tid; i < 64 * 64; i += 256) {
    int r = i >> 6, c = i & 63;
    xs[r * 65 + c] = x[(size_t)(row0 + r) * 64 + c];
  }
  #pragma unroll
  for (int i = tid; i < 3 * 64 * 64; i += 256) {
    int mat = i >> 12, rem = i & 4095;
    int c = rem >> 6, f = rem & 63;
    const float* W = (mat == 0) ? Wq : (mat == 1) ? Wk : Wv;
    ws[(mat * 64 + c) * 65 + f] = W[c * 64 + f];
  }
  __syncthreads();

  const int lane = tid & 31;
  const int w = tid >> 5;
  const int f0 = lane, f1 = lane + 32;

  float aq[2][8], ak[2][8], av[2][8];
  {
    float bq0 = bq[f0], bq1 = bq[f1];
    float bk0 = bk[f0], bk1 = bk[f1];
    float bv0 = bv[f0], bv1 = bv[f1];
    #pragma unroll
    for (int i = 0; i < 8; i++) {
      aq[0][i] = bq0; aq[1][i] = bq1;
      ak[0][i] = bk0; ak[1][i] = bk1;
      av[0][i] = bv0; av[1][i] = bv1;
    }
  }

  #pragma unroll 4
  for (int c = 0; c < 64; c++) {
    float wq0 = ws[(0 * 64 + c) * 65 + f0], wq1 = ws[(0 * 64 + c) * 65 + f1];
    float wk0 = ws[(1 * 64 + c) * 65 + f0], wk1 = ws[(1 * 64 + c) * 65 + f1];
    float wv0 = ws[(2 * 64 + c) * 65 + f0], wv1 = ws[(2 * 64 + c) * 65 + f1];
    #pragma unroll
    for (int i = 0; i < 8; i++) {
      float xv = xs[(w * 8 + i) * 65 + c];
      aq[0][i] += xv * wq0; aq[1][i] += xv * wq1;
      ak[0][i] += xv * wk0; ak[1][i] += xv * wk1;
      av[0][i] += xv * wv0; av[1][i] += xv * wv1;
    }
  }

  #pragma unroll
  for (int i = 0; i < 8; i++) {
    size_t base = (size_t)(row0 + w * 8 + i) * 64;
    g_Qh[base + f0] = __float2half_rn(aq[0][i] * LOG2E);
    g_Qh[base + f1] = __float2half_rn(aq[1][i] * LOG2E);
    g_Kh[base + f0] = __float2half_rn(ak[0][i]);
    g_Kh[base + f1] = __float2half_rn(ak[1][i]);
    g_V[base + f0] = av[0][i];
    g_V[base + f1] = av[1][i];
  }
}

// ---------------------------------------------------------------------------
// Pass 1: E' tile (128m x 128n) via fp16 MMA; P = 2^(E'-SHIFT2) -> bf16
// n-tile-major; row partial sums -> g_Sp.
// ---------------------------------------------------------------------------
__global__ __launch_bounds__(256, 2) void pass1_kernel() {
  extern __shared__ char sm1[];
  __half* qh = (__half*)sm1;                       // [128][72]
  __half* kh = (__half*)(sm1 + 128 * 72 * 2);      // [128][72]
  float* ssum = (float*)(sm1 + 2 * 128 * 72 * 2);  // [128]
  __nv_bfloat162* ps2 = (__nv_bfloat162*)sm1;      // overlay [128][68]

  const int b = blockIdx.z;
  const int m0 = blockIdx.y * 128;
  const int n0 = blockIdx.x * 128;
  const int tid = threadIdx.x;
  const __half* Qb = g_Qh + (size_t)b * NN * CC;
  const __half* Kb = g_Kh + (size_t)b * NN * CC;

  #pragma unroll
  for (int i = tid; i < 1024; i += 256) {
    int r = i >> 3, s = i & 7;
    cp16(&qh[r * 72 + s * 8], Qb + (size_t)(m0 + r) * 64 + s * 8);
    cp16(&kh[r * 72 + s * 8], Kb + (size_t)(n0 + r) * 64 + s * 8);
  }
  asm volatile("cp.async.commit_group;" ::: "memory");
  if (tid < 128) ssum[tid] = 0.0f;
  asm volatile("cp.async.wait_group 0;" ::: "memory");
  __syncthreads();

  const int lane = tid & 31;
  const int wid = tid >> 5;
  const int gid = lane >> 2, tig = lane & 3;
  const int mw = (wid >> 1) * 32;
  const int nw = (wid & 1) * 64;

  const int lq = lane & 7;
  const int lsel = lane >> 3;
  const int row_off = lq + ((lsel & 1) ? 8 : 0);
  const int col_off = (lsel & 2) ? 8 : 0;

  float acc[2][8][4];
  #pragma unroll
  for (int t = 0; t < 2; t++)
    #pragma unroll
    for (int j = 0; j < 8; j++)
      #pragma unroll
      for (int c = 0; c < 4; c++) acc[t][j][c] = 0.0f;

  #pragma unroll
  for (int k0 = 0; k0 < 64; k0 += 16) {
    unsigned a[2][4];
    #pragma unroll
    for (int t = 0; t < 2; t++)
      ldsm4(a[t][0], a[t][1], a[t][2], a[t][3],
            &qh[(mw + t * 16 + row_off) * 72 + k0 + col_off]);

    unsigned bf[8][2];
    #pragma unroll
    for (int j2 = 0; j2 < 4; j2++) {
      unsigned r0, r1, r2, r3;
      ldsm4(r0, r1, r2, r3, &kh[(nw + j2 * 16 + row_off) * 72 + k0 + col_off]);
      bf[2 * j2][0] = r0; bf[2 * j2 + 1][0] = r1;
      bf[2 * j2][1] = r2; bf[2 * j2 + 1][1] = r3;
    }

    #pragma unroll
    for (int t = 0; t < 2; t++)
      #pragma unroll
      for (int j = 0; j < 8; j++)
        mma_fp16(acc[t][j][0], acc[t][j][1], acc[t][j][2], acc[t][j][3],
                 a[t][0], a[t][1], a[t][2], a[t][3], bf[j][0], bf[j][1]);
  }

  __syncthreads();  // tile reads done; safe to overlay ps2

  #pragma unroll
  for (int t = 0; t < 2; t++) {
    float s0 = 0.0f, s1 = 0.0f;
    int r0 = mw + t * 16 + gid;
    #pragma unroll
    for (int j = 0; j < 8; j++) {
      float e0 = ex2(acc[t][j][0] - SHIFT2);
      float e1 = ex2(acc[t][j][1] - SHIFT2);
      float e2 = ex2(acc[t][j][2] - SHIFT2);
      float e3 = ex2(acc[t][j][3] - SHIFT2);
      s0 += e0 + e1;
      s1 += e2 + e3;
      int cp = (nw >> 1) + j * 4 + tig;
      ps2[r0 * 68 + cp] = __floats2bfloat162_rn(e0, e1);
      ps2[(r0 + 8) * 68 + cp] = __floats2bfloat162_rn(e2, e3);
    }
    s0 += __shfl_xor_sync(0xffffffffu, s0, 1);
    s0 += __shfl_xor_sync(0xffffffffu, s0, 2);
    s1 += __shfl_xor_sync(0xffffffffu, s1, 1);
    s1 += __shfl_xor_sync(0xffffffffu, s1, 2);
    if (tig == 0) {
      atomicAdd(&ssum[r0], s0);
      atomicAdd(&ssum[r0 + 8], s1);
    }
  }
  __syncthreads();

  if (tid < 128)
    g_Sp[((size_t)b * 32 + blockIdx.x) * NN + m0 + tid] = ssum[tid];

  uint4* GP4 = (uint4*)(g_P + (size_t)b * NN * NN);
  const int T = n0 >> 6;
  #pragma unroll
  for (int i = tid; i < 2048; i += 256) {
    int r = i >> 4, s = i & 15;
    GP4[((size_t)(T + (s >> 3)) * NN + (m0 + r)) * 8 + (s & 7)] =
        *(const uint4*)&ps2[r * 68 + s * 4];
  }
}

// ---------------------------------------------------------------------------
// norm: fused rsum + vscale (bf16 out). One warp per row.
// ---------------------------------------------------------------------------
__global__ __launch_bounds__(256) void norm_kernel() {
  const int row = blockIdx.x * 8 + (threadIdx.x >> 5);  // < NB*NN
  const int lane = threadIdx.x & 31;
  const int b = row >> 12, m = row & (NN - 1);

  float s = g_Sp[((size_t)b * 32 + lane) * NN + m];
  #pragma unroll
  for (int off = 16; off; off >>= 1) s += __shfl_xor_sync(0xffffffffu, s, off);
  const float rinv = 1.0f / s;

  size_t base = (size_t)row * 64;
  float v0 = g_V[base + 2 * lane], v1 = g_V[base + 2 * lane + 1];
  *(__nv_bfloat162*)&g_Vsb[base + 2 * lane] =
      __floats2bfloat162_rn(v0 * rinv, v1 * rinv);
}

// ---------------------------------------------------------------------------
// Pass 2: WIDE n-tile (256) to cut V smem traffic 4x; split-m into 4 quarters.
// grid (16 n-tiles, 4 m-quarters, NB) = 256 blocks.
// m-chunks of 32 rows; 3-slot ring; warp tile 32n x 64c (8 warps).
// smem: P [3][32][264], V [3][32][72] = 64512 B; 2 CTAs/SM.
// ---------------------------------------------------------------------------
#define NT 256
#define MC2 32
#define PST 264
__global__ __launch_bounds__(256, 2) void pass2_kernel() {
  extern __shared__ char sm[];
  __nv_bfloat16* praw = (__nv_bfloat16*)sm;                        // [3][32][264]
  __nv_bfloat16* vraw = (__nv_bfloat16*)(sm + 3 * MC2 * PST * 2);  // [3][32][72]

  const int b = blockIdx.z;
  const int quarter = blockIdx.y;
  const int n0 = blockIdx.x * NT;
  const int T0 = blockIdx.x * 4;           // first 64-wide P tile
  const int mbase = quarter * (NN / 4);
  const int tid = threadIdx.x;
  const int lane = tid & 31, wid = tid >> 5;
  const int gid = lane >> 2, tig = lane & 3;
  const int wn = wid * 32;                 // warp n-slice within 256

  const int lq = lane & 7;
  const int lsel = lane >> 3;
  const int a_row = lq + ((lsel & 2) ? 8 : 0);   // trans A (P^T): k row
  const int a_cofs = (lsel & 1) ? 8 : 0;         // n col offset
  const int b_row = lq + ((lsel & 1) ? 8 : 0);   // trans B (V): k row
  const int b_col = (lsel & 2) ? 8 : 0;          // c col offset

  const __nv_bfloat16* GPB = g_P + (size_t)b * NN * NN;
  const __nv_bfloat16* Vb = g_Vsb + (size_t)b * NN * CC;

  float acc[2][8][4];
  #pragma unroll
  for (int f = 0; f < 2; f++)
    #pragma unroll
    for (int j = 0; j < 8; j++)
      #pragma unroll
      for (int c = 0; c < 4; c++) acc[f][j][c] = 0.0f;

  #define ISSUE(bufe, mce)                                                      \
    {                                                                           \
      const int _buf = (bufe);                                                  \
      const int _mc = (mce);                                                    \
      _Pragma("unroll")                                                         \
      for (int ii = tid; ii < 1024; ii += 256) {                                \
        int tt = ii >> 8, rr = (ii >> 3) & 31, ss = ii & 7;                     \
        cp16(&praw[(_buf * MC2 + rr) * PST + tt * 64 + ss * 8],                 \
             GPB + ((size_t)(T0 + tt) * NN + _mc + rr) * 64 + ss * 8);          \
      }                                                                         \
      {                                                                         \
        int rr = tid >> 3, ss = tid & 7;                                        \
        cp16(&vraw[(_buf * MC2 + rr) * 72 + ss * 8],                            \
             Vb + (size_t)(_mc + rr) * 64 + ss * 8);                            \
      }                                                                         \
      asm volatile("cp.async.commit_group;" ::: "memory");                      \
    }

  ISSUE(0, mbase);
  ISSUE(1, mbase + MC2);
  const int NCH = (NN / 4) / MC2;  // 32 chunks per quarter
  for (int i = 0; i < NCH; i++) {
    if (i + 1 < NCH) {
      asm volatile("cp.async.wait_group 1;" ::: "memory");
    } else {
      asm volatile("cp.async.wait_group 0;" ::: "memory");
    }
    __syncthreads();  // chunk i visible; all warps done with iter i-1

    if (i + 2 < NCH) ISSUE((i + 2) % 3, mbase + (i + 2) * MC2);

    const __nv_bfloat16* pb = &praw[(i % 3) * MC2 * PST];
    const __nv_bfloat16* vb = &vraw[(i % 3) * MC2 * 72];

    #pragma unroll
    for (int k0 = 0; k0 < MC2; k0 += 16) {
      unsigned aA[2][4];
      #pragma unroll
      for (int f = 0; f < 2; f++)
        ldsm4t(aA[f][0], aA[f][1], aA[f][2], aA[f][3],
               &pb[(k0 + a_row) * PST + wn + f * 16 + a_cofs]);
      #pragma unroll
      for (int cj = 0; cj < 4; cj++) {
        unsigned b00, b01, b02, b03;
        ldsm4t(b00, b01, b02, b03, &vb[(k0 + b_row) * 72 + cj * 16 + b_col]);
        #pragma unroll
        for (int f = 0; f < 2; f++) {
          mma_bf16(acc[f][cj * 2][0], acc[f][cj * 2][1],
                   acc[f][cj * 2][2], acc[f][cj * 2][3],
                   aA[f][0], aA[f][1], aA[f][2], aA[f][3], b00, b01);
          mma_bf16(acc[f][cj * 2 + 1][0], acc[f][cj * 2 + 1][1],
                   acc[f][cj * 2 + 1][2], acc[f][cj * 2 + 1][3],
                   aA[f][0], aA[f][1], aA[f][2], aA[f][3], b02, b03);
        }
      }
    }
  }

  float* Po = g_Po[quarter];
  #pragma unroll
  for (int f = 0; f < 2; f++) {
    int n = n0 + wn + f * 16 + gid;
    #pragma unroll
    for (int j = 0; j < 8; j++) {
      int c = j * 8 + tig * 2;
      size_t i0 = ((size_t)b * NN + n) * 64 + c;
      *(float2*)&Po[i0] = make_float2(acc[f][j][0], acc[f][j][1]);
      size_t i1 = i0 + 8 * 64;  // n + 8
      *(float2*)&Po[i1] = make_float2(acc[f][j][2], acc[f][j][3]);
    }
  }
}

// ---------------------------------------------------------------------------
// combine: out = gamma * (Po0+Po1+Po2+Po3) + x   (float4 vectorized)
// ---------------------------------------------------------------------------
__global__ __launch_bounds__(256) void combine_kernel(
    const float* __restrict__ x, const float* __restrict__ gamma,
    float* __restrict__ out) {
  const int i = blockIdx.x * 256 + threadIdx.x;  // < NB*NN*CC/4
  const float g = gamma[0];
  float4 p0 = ((const float4*)g_Po[0])[i];
  float4 p1 = ((const float4*)g_Po[1])[i];
  float4 p2 = ((const float4*)g_Po[2])[i];
  float4 p3 = ((const float4*)g_Po[3])[i];
  float4 xv = ((const float4*)x)[i];
  float4 o;
  o.x = g * ((p0.x + p1.x) + (p2.x + p3.x)) + xv.x;
  o.y = g * ((p0.y + p1.y) + (p2.y + p3.y)) + xv.y;
  o.z = g * ((p0.z + p1.z) + (p2.z + p3.z)) + xv.z;
  o.w = g * ((p0.w + p1.w) + (p2.w + p3.w)) + xv.w;
  ((float4*)out)[i] = o;
}

// ---------------------------------------------------------------------------
extern "C" void kernel_launch(void* const* d_in, const int* in_sizes, int n_in,
                              void* d_out, int out_size) {
  const float* x  = (const float*)d_in[0];
  const float* Wq = (const float*)d_in[1];
  const float* bq = (const float*)d_in[2];
  const float* Wk = (const float*)d_in[3];
  const float* bk = (const float*)d_in[4];
  const float* Wv = (const float*)d_in[5];
  const float* bv = (const float*)d_in[6];
  const float* gamma = (const float*)d_in[7];
  float* out = (float*)d_out;

  const int smemq = (64 * 65 + 3 * 64 * 65) * 4;        // 66560
  const int smem1 = 2 * 128 * 72 * 2 + 128 * 4;         // 37376
  const int smem2 = 3 * MC2 * PST * 2 + 3 * MC2 * 72 * 2;  // 64512
  cudaFuncSetAttribute(qkv_kernel, cudaFuncAttributeMaxDynamicSharedMemorySize, smemq);
  cudaFuncSetAttribute(pass1_kernel, cudaFuncAttributeMaxDynamicSharedMemorySize, smem1);
  cudaFuncSetAttribute(pass2_kernel, cudaFuncAttributeMaxDynamicSharedMemorySize, smem2);

  qkv_kernel<<<(NB * NN) / 64, 256, smemq>>>(x, Wq, bq, Wk, bk, Wv, bv);
  pass1_kernel<<<dim3(NN / 128, NN / 128, NB), 256, smem1>>>();
  norm_kernel<<<(NB * NN) / 8, 256>>>();
  pass2_kernel<<<dim3(NN / NT, 4, NB), 256, smem2>>>();
  combine_kernel<<<(NB * NN * CC / 4) / 256, 256>>>(x, gamma, out);
}